// round 16
// baseline (speedup 1.0000x reference)
#include <cuda_runtime.h>
#include <cstdint>

// Chamfer distance, one-pass shared distance matrix.
// t' = (0.5|a|^2 + 0.5|b|^2) - a.b = d^2/2.  Row mins (over gt) and col mins
// (over pred) reduce the SAME t' values. Col mins cross the warp via
// redux.sync.min.s32 on float bits (exact here: negatives clamp to 0 later).
//
// R14 (86.5us): B-load ping-pong prefetch, APT=8/TPB=128, density 65% @ 35% occ.
// R15 (deferred col store) regressed: runtime store index + pending-reg copies
// cost +15% slots for +1pp density. REVERTED.
// R16: prefetch + HIGH occupancy: APT=4, TPB=256 (regs ~48 -> 5 blocks/SM,
// 40 warps, even 5+5 waves). Slots/pair rises 2.16->2.44 but density should
// go 0.65 -> ~0.75+ (R8 showed 60% density @ 52% occ WITHOUT prefetch).

#define TPB    256
#define NWARP  (TPB / 32)          // 8
#define APT    4                  // pred points per thread
#define ABLK   (TPB * APT)        // 1024 pred points per block
#define BT     272                // gt points per tile (mult of 4); 74 tiles
#define BTP    (BT + 4)           // padded for branchless prefetch overrun
#define MAXNP  20480              // >= 20000, multiple of ABLK
#define MAXNB  20128              // 74*272 >= 20000
#define MAX_BTILES (MAXNB / BT)   // 74
#define MAX_ATILES (MAXNP / ABLK) // 20
#define RTPB   256
#define MAX_RED  ((MAXNP + RTPB - 1) / RTPB)   // 80

__device__ float g_rmin[MAX_BTILES][MAXNP];
__device__ int   g_cmin[MAX_ATILES][MAXNB];
__device__ float g_bsum[2 * MAX_RED];

#define F32_INF __int_as_float(0x7f800000)

#define LDS_V2U64(v0, v1, base, OFF)                                     \
    asm volatile("ld.shared.v2.u64 {%0,%1}, [%2+" #OFF "];"              \
                 : "=l"(v0), "=l"(v1) : "r"(base))

#define ADD2(out, a, b)                                                  \
    asm("add.rn.f32x2 %0, %1, %2;" : "=l"(out) : "l"(a), "l"(b))

// t = fma(nx, x01, hab); t = fma(ny, y01, t); t = fma(nz, z01, t); unpack.
#define PAIR_DIST(lo, hi, nx, ny, nz, x01, y01, z01, hab)                \
    asm("{\n\t.reg .b64 t;\n\t"                                          \
        "fma.rn.f32x2 t, %2, %3, %8;\n\t"                                \
        "fma.rn.f32x2 t, %4, %5, t;\n\t"                                 \
        "fma.rn.f32x2 t, %6, %7, t;\n\t"                                 \
        "mov.b64 {%0,%1}, t;\n\t}"                                       \
        : "=f"(lo), "=f"(hi)                                             \
        : "l"(nx), "l"(x01), "l"(ny), "l"(y01), "l"(nz), "l"(z01), "l"(hab))

__device__ __forceinline__ int redux_min_s32(int v) {
    int r;
    asm("redux.sync.min.s32 %0, %1, 0xffffffff;" : "=r"(r) : "r"(v));
    return r;
}

__global__ __launch_bounds__(TPB)
void cd_tile_kernel(const float* __restrict__ pred, int nP,
                    const float* __restrict__ gt,   int nG)
{
    __shared__ __align__(16) float tileF[BTP * 4]; // per 2 B pts: {x0,x1,y0,y1,z0,z1,h0,h1}
    __shared__ int col_acc[NWARP][BT];             // per-warp col mins (each col written once)

    const int warp = threadIdx.x >> 5;
    const int lane = threadIdx.x & 31;

    // A = pred points, clamped-duplicate padding (dups harmless for col mins;
    // row writes guarded by original index).
    const int a0 = blockIdx.x * ABLK + threadIdx.x;
    unsigned long long NX[APT], NY[APT], NZ[APT], HA[APT];
    #pragma unroll
    for (int k = 0; k < APT; k++) {
        const int ac = min(a0 + k * TPB, nP - 1);
        const float ax = pred[ac * 3 + 0];
        const float ay = pred[ac * 3 + 1];
        const float az = pred[ac * 3 + 2];
        const float nax = -ax, nay = -ay, naz = -az;
        const float ha = 0.5f * (ax * ax + ay * ay + az * az);
        asm("mov.b64 %0, {%1,%1};" : "=l"(NX[k]) : "f"(nax));
        asm("mov.b64 %0, {%1,%1};" : "=l"(NY[k]) : "f"(nay));
        asm("mov.b64 %0, {%1,%1};" : "=l"(NZ[k]) : "f"(naz));
        asm("mov.b64 %0, {%1,%1};" : "=l"(HA[k]) : "f"(ha));
    }

    // B tile = gt points; pad BOTH the tail-of-data and the prefetch overrun
    // region with copies of the last point.
    const int b0 = blockIdx.y * BT;
    for (int j = threadIdx.x; j < BTP; j += TPB) {
        const int bi = min(b0 + min(j, BT - 1), nG - 1);
        const float bx = gt[bi * 4 + 0];
        const float by = gt[bi * 4 + 1];
        const float bz = gt[bi * 4 + 2];
        const float hb = 0.5f * (bx * bx + by * by + bz * bz);
        const int g = j >> 1, l = j & 1, o = g * 8 + l;
        tileF[o + 0] = bx;
        tileF[o + 2] = by;
        tileF[o + 4] = bz;
        tileF[o + 6] = hb;
    }
    __syncthreads();

    float mlo[APT], mhi[APT];
    #pragma unroll
    for (int k = 0; k < APT; k++) { mlo[k] = F32_INF; mhi[k] = F32_INF; }

    unsigned int saddr = (unsigned int)__cvta_generic_to_shared(tileF);

    // GROUP: process one prefetched B pair (2 columns), scalar-min paths,
    // immediate lane0 store (compile-time column offsets).
    #define GROUP(XR, YR, ZR, HR, COL)                                       \
    {                                                                        \
        unsigned long long HAB;                                              \
        float lo, hi;                                                        \
        int cl, ch;                                                          \
        ADD2(HAB, HR, HA[0]);                                                \
        PAIR_DIST(lo, hi, NX[0], NY[0], NZ[0], XR, YR, ZR, HAB);             \
        mlo[0] = fminf(mlo[0], lo);  mhi[0] = fminf(mhi[0], hi);             \
        cl = __float_as_int(lo);  ch = __float_as_int(hi);                   \
        _Pragma("unroll")                                                    \
        for (int k = 1; k < APT; k++) {                                      \
            ADD2(HAB, HR, HA[k]);                                            \
            PAIR_DIST(lo, hi, NX[k], NY[k], NZ[k], XR, YR, ZR, HAB);         \
            mlo[k] = fminf(mlo[k], lo);  mhi[k] = fminf(mhi[k], hi);         \
            cl = min(cl, __float_as_int(lo));                                \
            ch = min(ch, __float_as_int(hi));                                \
        }                                                                    \
        cl = redux_min_s32(cl);                                              \
        ch = redux_min_s32(ch);                                              \
        if (lane == 0) {                                                     \
            col_acc[warp][(COL) + 0] = cl;                                   \
            col_acc[warp][(COL) + 1] = ch;                                   \
        }                                                                    \
    }

    {
        unsigned long long X0, Y0, Z0, H0, X1, Y1, Z1, H1;
        LDS_V2U64(X0, Y0, saddr, 0);
        LDS_V2U64(Z0, H0, saddr, 16);
        for (int jb = 0; jb < BT; jb += 4) {
            LDS_V2U64(X1, Y1, saddr, 32);       // prefetch group g+1
            LDS_V2U64(Z1, H1, saddr, 48);
            GROUP(X0, Y0, Z0, H0, jb + 0)
            LDS_V2U64(X0, Y0, saddr, 64);       // prefetch group g+2 (pad-safe)
            LDS_V2U64(Z0, H0, saddr, 80);
            GROUP(X1, Y1, Z1, H1, jb + 2)
            saddr += 64;
        }
    }
    #undef GROUP

    // Row partials: min over this B tile for each owned pred point.
    #pragma unroll
    for (int k = 0; k < APT; k++) {
        const int a = a0 + k * TPB;
        if (a < nP)
            g_rmin[blockIdx.y][a] = fminf(mlo[k], mhi[k]);
    }

    // Col partials: combine NWARP warps, write this block's B range (int bits).
    __syncthreads();
    for (int j = threadIdx.x; j < BT; j += TPB) {
        int m = col_acc[0][j];
        #pragma unroll
        for (int w = 1; w < NWARP; w++)
            m = min(m, col_acc[w][j]);
        g_cmin[blockIdx.x][b0 + j] = m;     // padded slots written, never read
    }
}

// Fused row+col partial reduction: blocks [0,redA) handle rows, rest cols.
__global__ __launch_bounds__(RTPB)
void cd_red(int nP, int nG, int nbt, int nat, int redA)
{
    float v = 0.f;
    if (blockIdx.x < redA) {
        const int i = blockIdx.x * RTPB + threadIdx.x;
        if (i < nP) {
            float m = g_rmin[0][i];
            for (int t = 1; t < nbt; t++)
                m = fminf(m, g_rmin[t][i]);
            v = fmaxf(2.f * m, 0.f) / (float)nP;
        }
    } else {
        const int j = (blockIdx.x - redA) * RTPB + threadIdx.x;
        if (j < nG) {
            int m = g_cmin[0][j];
            for (int t = 1; t < nat; t++)
                m = min(m, g_cmin[t][j]);
            v = fmaxf(2.f * __int_as_float(m), 0.f) / (float)nG;
        }
    }
    __shared__ float sm[RTPB];
    sm[threadIdx.x] = v;
    __syncthreads();
    for (int s = RTPB / 2; s > 0; s >>= 1) {
        if (threadIdx.x < s) sm[threadIdx.x] += sm[threadIdx.x + s];
        __syncthreads();
    }
    if (threadIdx.x == 0) g_bsum[blockIdx.x] = sm[0];
}

__global__ __launch_bounds__(RTPB)
void cd_final(float* __restrict__ out, int n)
{
    float v = 0.f;
    for (int i = threadIdx.x; i < n; i += RTPB)
        v += g_bsum[i];
    __shared__ float sm[RTPB];
    sm[threadIdx.x] = v;
    __syncthreads();
    for (int s = RTPB / 2; s > 0; s >>= 1) {
        if (threadIdx.x < s) sm[threadIdx.x] += sm[threadIdx.x + s];
        __syncthreads();
    }
    if (threadIdx.x == 0) out[0] = sm[0];
}

extern "C" void kernel_launch(void* const* d_in, const int* in_sizes, int n_in,
                              void* d_out, int out_size)
{
    // pred has 3 columns (smaller buffer), gt has 4. Robust to input order.
    const float* pred;
    const float* gt;
    int szP, szG;
    if (in_sizes[0] <= in_sizes[1]) {
        pred = (const float*)d_in[0]; szP = in_sizes[0];
        gt   = (const float*)d_in[1]; szG = in_sizes[1];
    } else {
        pred = (const float*)d_in[1]; szP = in_sizes[1];
        gt   = (const float*)d_in[0]; szG = in_sizes[0];
    }
    const int nP = szP / 3;
    const int nG = szG / 4;

    const int atiles = (nP + ABLK - 1) / ABLK;      // 20
    const int btiles = (nG + BT - 1) / BT;          // 74

    dim3 grid(atiles, btiles);
    cd_tile_kernel<<<grid, TPB>>>(pred, nP, gt, nG);

    const int redA = (nP + RTPB - 1) / RTPB;        // 79
    const int redB = (nG + RTPB - 1) / RTPB;        // 79
    cd_red<<<redA + redB, RTPB>>>(nP, nG, btiles, atiles, redA);
    cd_final<<<1, RTPB>>>((float*)d_out, redA + redB);
}

// round 17
// speedup vs baseline: 1.0231x; 1.0231x over previous
#include <cuda_runtime.h>
#include <cstdint>

// Chamfer distance, one-pass shared distance matrix.
// t' = (0.5|a|^2 + 0.5|b|^2) - a.b = d^2/2.  Row mins (over gt) and col mins
// (over pred) reduce the SAME t' values. Col mins cross the warp via
// redux.sync.min.s32 on float bits (exact here: negatives clamp to 0 later).
//
// R14 (86.5us): APT=8/TPB=128, B ping-pong prefetch, density 65% @ 35% occ.
// R15 (runtime-indexed deferred store) and R16 (high-occ APT=4) both regressed.
// R17: 4-group unrolled iteration; all four lane0 col-stores issue at the END
// of the iteration at compile-time offsets, so groups 0-2's REDUX results are
// long drained when stored; only group 3's redux tail stays exposed (~25 cyc
// per 280 slots instead of per 70).

#define TPB    128
#define NWARP  (TPB / 32)          // 4
#define APT    8                  // pred points per thread
#define ABLK   (TPB * APT)        // 1024 pred points per block
#define BT     272                // gt points per tile (mult of 8); 74 tiles
#define BTP    (BT + 4)           // padded for branchless prefetch overrun
#define MAXNP  20480              // >= 20000, multiple of ABLK
#define MAXNB  20128              // 74*272 >= 20000
#define MAX_BTILES (MAXNB / BT)   // 74
#define MAX_ATILES (MAXNP / ABLK) // 20
#define RTPB   256
#define MAX_RED  ((MAXNP + RTPB - 1) / RTPB)   // 80

__device__ float g_rmin[MAX_BTILES][MAXNP];
__device__ int   g_cmin[MAX_ATILES][MAXNB];
__device__ float g_bsum[2 * MAX_RED];

#define F32_INF __int_as_float(0x7f800000)

#define LDS_V2U64(v0, v1, base, OFF)                                     \
    asm volatile("ld.shared.v2.u64 {%0,%1}, [%2+" #OFF "];"              \
                 : "=l"(v0), "=l"(v1) : "r"(base))

#define ADD2(out, a, b)                                                  \
    asm("add.rn.f32x2 %0, %1, %2;" : "=l"(out) : "l"(a), "l"(b))

// t = fma(nx, x01, hab); t = fma(ny, y01, t); t = fma(nz, z01, t); unpack.
#define PAIR_DIST(lo, hi, nx, ny, nz, x01, y01, z01, hab)                \
    asm("{\n\t.reg .b64 t;\n\t"                                          \
        "fma.rn.f32x2 t, %2, %3, %8;\n\t"                                \
        "fma.rn.f32x2 t, %4, %5, t;\n\t"                                 \
        "fma.rn.f32x2 t, %6, %7, t;\n\t"                                 \
        "mov.b64 {%0,%1}, t;\n\t}"                                       \
        : "=f"(lo), "=f"(hi)                                             \
        : "l"(nx), "l"(x01), "l"(ny), "l"(y01), "l"(nz), "l"(z01), "l"(hab))

__device__ __forceinline__ int redux_min_s32(int v) {
    int r;
    asm("redux.sync.min.s32 %0, %1, 0xffffffff;" : "=r"(r) : "r"(v));
    return r;
}

__global__ __launch_bounds__(TPB)
void cd_tile_kernel(const float* __restrict__ pred, int nP,
                    const float* __restrict__ gt,   int nG)
{
    __shared__ __align__(16) float tileF[BTP * 4]; // per 2 B pts: {x0,x1,y0,y1,z0,z1,h0,h1}
    __shared__ int col_acc[NWARP][BT];             // per-warp col mins (each col written once)

    const int warp = threadIdx.x >> 5;
    const int lane = threadIdx.x & 31;

    // A = pred points, clamped-duplicate padding (dups harmless for col mins;
    // row writes guarded by original index).
    const int a0 = blockIdx.x * ABLK + threadIdx.x;
    unsigned long long NX[APT], NY[APT], NZ[APT], HA[APT];
    #pragma unroll
    for (int k = 0; k < APT; k++) {
        const int ac = min(a0 + k * TPB, nP - 1);
        const float ax = pred[ac * 3 + 0];
        const float ay = pred[ac * 3 + 1];
        const float az = pred[ac * 3 + 2];
        const float nax = -ax, nay = -ay, naz = -az;
        const float ha = 0.5f * (ax * ax + ay * ay + az * az);
        asm("mov.b64 %0, {%1,%1};" : "=l"(NX[k]) : "f"(nax));
        asm("mov.b64 %0, {%1,%1};" : "=l"(NY[k]) : "f"(nay));
        asm("mov.b64 %0, {%1,%1};" : "=l"(NZ[k]) : "f"(naz));
        asm("mov.b64 %0, {%1,%1};" : "=l"(HA[k]) : "f"(ha));
    }

    // B tile = gt points; pad BOTH the tail-of-data and the prefetch overrun
    // region with copies of the last point.
    const int b0 = blockIdx.y * BT;
    for (int j = threadIdx.x; j < BTP; j += TPB) {
        const int bi = min(b0 + min(j, BT - 1), nG - 1);
        const float bx = gt[bi * 4 + 0];
        const float by = gt[bi * 4 + 1];
        const float bz = gt[bi * 4 + 2];
        const float hb = 0.5f * (bx * bx + by * by + bz * bz);
        const int g = j >> 1, l = j & 1, o = g * 8 + l;
        tileF[o + 0] = bx;
        tileF[o + 2] = by;
        tileF[o + 4] = bz;
        tileF[o + 6] = hb;
    }
    __syncthreads();

    float mlo[APT], mhi[APT];
    #pragma unroll
    for (int k = 0; k < APT; k++) { mlo[k] = F32_INF; mhi[k] = F32_INF; }

    unsigned int saddr = (unsigned int)__cvta_generic_to_shared(tileF);

    // GROUPC: math + per-thread mins + redux into (CLV, CHV). No store.
    #define GROUPC(XR, YR, ZR, HR, CLV, CHV)                                 \
    {                                                                        \
        unsigned long long HAB;                                              \
        float lo, hi;                                                        \
        ADD2(HAB, HR, HA[0]);                                                \
        PAIR_DIST(lo, hi, NX[0], NY[0], NZ[0], XR, YR, ZR, HAB);             \
        mlo[0] = fminf(mlo[0], lo);  mhi[0] = fminf(mhi[0], hi);             \
        CLV = __float_as_int(lo);  CHV = __float_as_int(hi);                 \
        _Pragma("unroll")                                                    \
        for (int k = 1; k < APT; k++) {                                      \
            ADD2(HAB, HR, HA[k]);                                            \
            PAIR_DIST(lo, hi, NX[k], NY[k], NZ[k], XR, YR, ZR, HAB);         \
            mlo[k] = fminf(mlo[k], lo);  mhi[k] = fminf(mhi[k], hi);         \
            CLV = min(CLV, __float_as_int(lo));                              \
            CHV = min(CHV, __float_as_int(hi));                              \
        }                                                                    \
        CLV = redux_min_s32(CLV);                                            \
        CHV = redux_min_s32(CHV);                                            \
    }

    #define STOREC(CLV, CHV, COL)                                            \
        if (lane == 0) {                                                     \
            col_acc[warp][(COL) + 0] = CLV;                                  \
            col_acc[warp][(COL) + 1] = CHV;                                  \
        }

    {
        unsigned long long X0, Y0, Z0, H0, X1, Y1, Z1, H1;
        int cl0, ch0, cl1, ch1, cl2, ch2, cl3, ch3;
        LDS_V2U64(X0, Y0, saddr, 0);
        LDS_V2U64(Z0, H0, saddr, 16);
        for (int jb = 0; jb < BT; jb += 8) {
            LDS_V2U64(X1, Y1, saddr, 32);          // prefetch group g+1
            LDS_V2U64(Z1, H1, saddr, 48);
            GROUPC(X0, Y0, Z0, H0, cl0, ch0)       // cols jb+0, jb+1
            LDS_V2U64(X0, Y0, saddr, 64);          // prefetch group g+2
            LDS_V2U64(Z0, H0, saddr, 80);
            GROUPC(X1, Y1, Z1, H1, cl1, ch1)       // cols jb+2, jb+3
            LDS_V2U64(X1, Y1, saddr, 96);          // prefetch group g+3
            LDS_V2U64(Z1, H1, saddr, 112);
            GROUPC(X0, Y0, Z0, H0, cl2, ch2)       // cols jb+4, jb+5
            LDS_V2U64(X0, Y0, saddr, 128);         // prefetch group g+4 (pad-safe)
            LDS_V2U64(Z0, H0, saddr, 144);
            GROUPC(X1, Y1, Z1, H1, cl3, ch3)       // cols jb+6, jb+7
            STOREC(cl0, ch0, jb + 0)               // redux long drained
            STOREC(cl1, ch1, jb + 2)
            STOREC(cl2, ch2, jb + 4)
            STOREC(cl3, ch3, jb + 6)               // only this one's tail exposed
            saddr += 128;
        }
    }
    #undef GROUPC
    #undef STOREC

    // Row partials: min over this B tile for each owned pred point.
    #pragma unroll
    for (int k = 0; k < APT; k++) {
        const int a = a0 + k * TPB;
        if (a < nP)
            g_rmin[blockIdx.y][a] = fminf(mlo[k], mhi[k]);
    }

    // Col partials: combine NWARP warps, write this block's B range (int bits).
    __syncthreads();
    for (int j = threadIdx.x; j < BT; j += TPB) {
        int m = col_acc[0][j];
        #pragma unroll
        for (int w = 1; w < NWARP; w++)
            m = min(m, col_acc[w][j]);
        g_cmin[blockIdx.x][b0 + j] = m;     // padded slots written, never read
    }
}

// Fused row+col partial reduction: blocks [0,redA) handle rows, rest cols.
__global__ __launch_bounds__(RTPB)
void cd_red(int nP, int nG, int nbt, int nat, int redA)
{
    float v = 0.f;
    if (blockIdx.x < redA) {
        const int i = blockIdx.x * RTPB + threadIdx.x;
        if (i < nP) {
            float m = g_rmin[0][i];
            for (int t = 1; t < nbt; t++)
                m = fminf(m, g_rmin[t][i]);
            v = fmaxf(2.f * m, 0.f) / (float)nP;
        }
    } else {
        const int j = (blockIdx.x - redA) * RTPB + threadIdx.x;
        if (j < nG) {
            int m = g_cmin[0][j];
            for (int t = 1; t < nat; t++)
                m = min(m, g_cmin[t][j]);
            v = fmaxf(2.f * __int_as_float(m), 0.f) / (float)nG;
        }
    }
    __shared__ float sm[RTPB];
    sm[threadIdx.x] = v;
    __syncthreads();
    for (int s = RTPB / 2; s > 0; s >>= 1) {
        if (threadIdx.x < s) sm[threadIdx.x] += sm[threadIdx.x + s];
        __syncthreads();
    }
    if (threadIdx.x == 0) g_bsum[blockIdx.x] = sm[0];
}

__global__ __launch_bounds__(RTPB)
void cd_final(float* __restrict__ out, int n)
{
    float v = 0.f;
    for (int i = threadIdx.x; i < n; i += RTPB)
        v += g_bsum[i];
    __shared__ float sm[RTPB];
    sm[threadIdx.x] = v;
    __syncthreads();
    for (int s = RTPB / 2; s > 0; s >>= 1) {
        if (threadIdx.x < s) sm[threadIdx.x] += sm[threadIdx.x + s];
        __syncthreads();
    }
    if (threadIdx.x == 0) out[0] = sm[0];
}

extern "C" void kernel_launch(void* const* d_in, const int* in_sizes, int n_in,
                              void* d_out, int out_size)
{
    // pred has 3 columns (smaller buffer), gt has 4. Robust to input order.
    const float* pred;
    const float* gt;
    int szP, szG;
    if (in_sizes[0] <= in_sizes[1]) {
        pred = (const float*)d_in[0]; szP = in_sizes[0];
        gt   = (const float*)d_in[1]; szG = in_sizes[1];
    } else {
        pred = (const float*)d_in[1]; szP = in_sizes[1];
        gt   = (const float*)d_in[0]; szG = in_sizes[0];
    }
    const int nP = szP / 3;
    const int nG = szG / 4;

    const int atiles = (nP + ABLK - 1) / ABLK;      // 20
    const int btiles = (nG + BT - 1) / BT;          // 74

    dim3 grid(atiles, btiles);
    cd_tile_kernel<<<grid, TPB>>>(pred, nP, gt, nG);

    const int redA = (nP + RTPB - 1) / RTPB;        // 79
    const int redB = (nG + RTPB - 1) / RTPB;        // 79
    cd_red<<<redA + redB, RTPB>>>(nP, nG, btiles, atiles, redA);
    cd_final<<<1, RTPB>>>((float*)d_out, redA + redB);
}